// round 2
// baseline (speedup 1.0000x reference)
#include <cuda_runtime.h>
#include <math_constants.h>

// ---------------------------------------------------------------------------
// Problem constants
// ---------------------------------------------------------------------------
#define BATCH   262144
#define GCOMP   25
#define DDIM    4
#define H1      128
#define H2      256
#define H3      200
#define NHEAD   300          // 3 * G * D  (mu | sig | pai), order: head*100 + g*4 + d
#define H3P     208          // H3 padded to /16B
#define NHEADP  304          // NHEAD padded

// rows per block
#define ROWS    32
#define THREADS 256

// ---------------------------------------------------------------------------
// Device scratch: transposed, padded weights (k-major) + packed head bias
// ---------------------------------------------------------------------------
__device__ __align__(16) float g_W2t[H1 * H2];        // [k=128][c=256]
__device__ __align__(16) float g_W3t[H2 * H3P];       // [k=256][c=208] zero-padded
__device__ __align__(16) float g_Wh [H3 * NHEADP];    // [k=200][o=304] zero-padded
__device__ __align__(16) float g_bh [NHEADP];

// ---------------------------------------------------------------------------
// Prep kernel: build transposed weight layouts (runs once per launch; ~150k elems)
// ---------------------------------------------------------------------------
__global__ void prep_kernel(const float* __restrict__ W2,
                            const float* __restrict__ W3,
                            const float* __restrict__ Wmu,
                            const float* __restrict__ Wsig,
                            const float* __restrict__ Wpai,
                            const float* __restrict__ bmu,
                            const float* __restrict__ bsig,
                            const float* __restrict__ bpai)
{
    const int t = blockIdx.x * blockDim.x + threadIdx.x;

    if (t < H1 * H2) {                       // W2t[k][c] = W2[c][k]
        int k = t / H2, c = t % H2;
        g_W2t[t] = W2[c * H1 + k];
    }
    {
        int t2 = t - H1 * H2;
        if (t2 >= 0 && t2 < H2 * H3P) {      // W3t[k][c] = W3[c][k], pad c>=200
            int k = t2 / H3P, c = t2 % H3P;
            g_W3t[t2] = (c < H3) ? W3[c * H2 + k] : 0.f;
        }
    }
    {
        int t3 = t - H1 * H2 - H2 * H3P;
        if (t3 >= 0 && t3 < H3 * NHEADP) {   // Wh[k][o] with o = head*100 + (g*4+d)
            int k = t3 / NHEADP, o = t3 % NHEADP;
            float v = 0.f;
            if (o < NHEAD) {
                int h = o / 100, rem = o % 100;  // rem = g*D + d
                const float* W = (h == 0) ? Wmu : ((h == 1) ? Wsig : Wpai);
                v = W[rem * H3 + k];             // W shape (G,D,H3) flattened
            }
            g_Wh[t3] = v;
        }
    }
    {
        int t4 = t - H1 * H2 - H2 * H3P - H3 * NHEADP;
        if (t4 >= 0 && t4 < NHEADP) {
            float v = 0.f;
            if (t4 < NHEAD) {
                int h = t4 / 100, rem = t4 % 100;
                const float* bb = (h == 0) ? bmu : ((h == 1) ? bsig : bpai);
                v = bb[rem];
            }
            g_bh[t4] = v;
        }
    }
}

// ---------------------------------------------------------------------------
// SMEM layout (in floats). Lifetimes:
//   h1 ends after phase2, h2 ends after phase3, h3 ends after phase4.
//   hout reuses the h2+h1 region.
// ---------------------------------------------------------------------------
#define O_H2    0                      // 32*260 = 8320
#define O_H1    8320                   // 32*132 = 4224  -> 12544
#define O_H3    12544                  // 32*208 = 6656  -> 19200
#define O_HOUT  0                      // 32*304 = 9728  (fits inside 12544)
#define O_GUM   19200                  // 32*100 = 3200  -> 22400
#define O_X0    22400                  // 96             -> 22496
#define SMEM_FLOATS 22496
#define SMEM_BYTES  (SMEM_FLOATS * 4)  // 89984 B -> 2 blocks/SM

#define S_H1 132
#define S_H2 260
#define S_H3 208
#define S_HO 304

__global__ __launch_bounds__(THREADS)
void mdn_kernel(const float* __restrict__ x0,
                const float* __restrict__ randv,
                const float* __restrict__ gumbel,
                const float* __restrict__ W1,
                const float* __restrict__ b1,
                const float* __restrict__ b2,
                const float* __restrict__ b3,
                float* __restrict__ out)
{
    extern __shared__ float sm[];
    float* h1s   = sm + O_H1;
    float* h2s   = sm + O_H2;
    float* h3s   = sm + O_H3;
    float* houts = sm + O_HOUT;
    float* gums  = sm + O_GUM;
    float* x0s   = sm + O_X0;

    const int t    = threadIdx.x;
    const int row0 = blockIdx.x * ROWS;

    // ---- phase 0: x0 tile (32 rows x 3, contiguous 96 floats) ----
    if (t < ROWS * 3) x0s[t] = x0[row0 * 3 + t];
    __syncthreads();

    // ---- phase 1: h1 = relu(x0 @ W1^T + b1)  (32x128 outputs) ----
#pragma unroll
    for (int i = 0; i < (ROWS * H1) / THREADS; i++) {
        int o = t + i * THREADS;
        int r = o >> 7;          // /128
        int c = o & 127;
        float acc = b1[c];
        acc = fmaf(x0s[r * 3 + 0], W1[c * 3 + 0], acc);
        acc = fmaf(x0s[r * 3 + 1], W1[c * 3 + 1], acc);
        acc = fmaf(x0s[r * 3 + 2], W1[c * 3 + 2], acc);
        h1s[r * S_H1 + c] = fmaxf(acc, 0.f);
    }
    __syncthreads();

    const int ty = t >> 5;        // 0..7  (row group of 4)
    const int tx = t & 31;        // 0..31 (col group of 4)
    const int r0 = ty * 4;

    // ---- phase 2: h2 = relu(h1 @ W2^T + b2)  K=128, N=256, 2 passes ----
    for (int p = 0; p < 2; p++) {
        int cb = p * 128 + tx * 4;
        float4 bias = *(const float4*)&b2[cb];
        float4 a0 = bias, a1 = bias, a2 = bias, a3 = bias;
#pragma unroll 4
        for (int k = 0; k < H1; k++) {
            float4 w = *(const float4*)&g_W2t[k * H2 + cb];
            float x;
            x = h1s[(r0 + 0) * S_H1 + k];
            a0.x = fmaf(x, w.x, a0.x); a0.y = fmaf(x, w.y, a0.y);
            a0.z = fmaf(x, w.z, a0.z); a0.w = fmaf(x, w.w, a0.w);
            x = h1s[(r0 + 1) * S_H1 + k];
            a1.x = fmaf(x, w.x, a1.x); a1.y = fmaf(x, w.y, a1.y);
            a1.z = fmaf(x, w.z, a1.z); a1.w = fmaf(x, w.w, a1.w);
            x = h1s[(r0 + 2) * S_H1 + k];
            a2.x = fmaf(x, w.x, a2.x); a2.y = fmaf(x, w.y, a2.y);
            a2.z = fmaf(x, w.z, a2.z); a2.w = fmaf(x, w.w, a2.w);
            x = h1s[(r0 + 3) * S_H1 + k];
            a3.x = fmaf(x, w.x, a3.x); a3.y = fmaf(x, w.y, a3.y);
            a3.z = fmaf(x, w.z, a3.z); a3.w = fmaf(x, w.w, a3.w);
        }
        a0.x = fmaxf(a0.x, 0.f); a0.y = fmaxf(a0.y, 0.f); a0.z = fmaxf(a0.z, 0.f); a0.w = fmaxf(a0.w, 0.f);
        a1.x = fmaxf(a1.x, 0.f); a1.y = fmaxf(a1.y, 0.f); a1.z = fmaxf(a1.z, 0.f); a1.w = fmaxf(a1.w, 0.f);
        a2.x = fmaxf(a2.x, 0.f); a2.y = fmaxf(a2.y, 0.f); a2.z = fmaxf(a2.z, 0.f); a2.w = fmaxf(a2.w, 0.f);
        a3.x = fmaxf(a3.x, 0.f); a3.y = fmaxf(a3.y, 0.f); a3.z = fmaxf(a3.z, 0.f); a3.w = fmaxf(a3.w, 0.f);
        *(float4*)&h2s[(r0 + 0) * S_H2 + cb] = a0;
        *(float4*)&h2s[(r0 + 1) * S_H2 + cb] = a1;
        *(float4*)&h2s[(r0 + 2) * S_H2 + cb] = a2;
        *(float4*)&h2s[(r0 + 3) * S_H2 + cb] = a3;
    }
    __syncthreads();

    // ---- phase 3: h3 = relu(h2 @ W3^T + b3)  K=256, N=200 (pad 208), 2 passes ----
    for (int p = 0; p < 2; p++) {
        int cb = p * 128 + tx * 4;
        if (cb < H3P) {
            float4 bias;
            bias.x = (cb + 0 < H3) ? b3[cb + 0] : 0.f;
            bias.y = (cb + 1 < H3) ? b3[cb + 1] : 0.f;
            bias.z = (cb + 2 < H3) ? b3[cb + 2] : 0.f;
            bias.w = (cb + 3 < H3) ? b3[cb + 3] : 0.f;
            float4 a0 = bias, a1 = bias, a2 = bias, a3 = bias;
#pragma unroll 4
            for (int k = 0; k < H2; k++) {
                float4 w = *(const float4*)&g_W3t[k * H3P + cb];
                float x;
                x = h2s[(r0 + 0) * S_H2 + k];
                a0.x = fmaf(x, w.x, a0.x); a0.y = fmaf(x, w.y, a0.y);
                a0.z = fmaf(x, w.z, a0.z); a0.w = fmaf(x, w.w, a0.w);
                x = h2s[(r0 + 1) * S_H2 + k];
                a1.x = fmaf(x, w.x, a1.x); a1.y = fmaf(x, w.y, a1.y);
                a1.z = fmaf(x, w.z, a1.z); a1.w = fmaf(x, w.w, a1.w);
                x = h2s[(r0 + 2) * S_H2 + k];
                a2.x = fmaf(x, w.x, a2.x); a2.y = fmaf(x, w.y, a2.y);
                a2.z = fmaf(x, w.z, a2.z); a2.w = fmaf(x, w.w, a2.w);
                x = h2s[(r0 + 3) * S_H2 + k];
                a3.x = fmaf(x, w.x, a3.x); a3.y = fmaf(x, w.y, a3.y);
                a3.z = fmaf(x, w.z, a3.z); a3.w = fmaf(x, w.w, a3.w);
            }
            a0.x = fmaxf(a0.x, 0.f); a0.y = fmaxf(a0.y, 0.f); a0.z = fmaxf(a0.z, 0.f); a0.w = fmaxf(a0.w, 0.f);
            a1.x = fmaxf(a1.x, 0.f); a1.y = fmaxf(a1.y, 0.f); a1.z = fmaxf(a1.z, 0.f); a1.w = fmaxf(a1.w, 0.f);
            a2.x = fmaxf(a2.x, 0.f); a2.y = fmaxf(a2.y, 0.f); a2.z = fmaxf(a2.z, 0.f); a2.w = fmaxf(a2.w, 0.f);
            a3.x = fmaxf(a3.x, 0.f); a3.y = fmaxf(a3.y, 0.f); a3.z = fmaxf(a3.z, 0.f); a3.w = fmaxf(a3.w, 0.f);
            *(float4*)&h3s[(r0 + 0) * S_H3 + cb] = a0;
            *(float4*)&h3s[(r0 + 1) * S_H3 + cb] = a1;
            *(float4*)&h3s[(r0 + 2) * S_H3 + cb] = a2;
            *(float4*)&h3s[(r0 + 3) * S_H3 + cb] = a3;
        }
    }
    __syncthreads();

    // ---- gumbel tile load (coalesced) ----
    for (int i = t; i < ROWS * GCOMP * DDIM; i += THREADS)
        gums[i] = gumbel[row0 * (GCOMP * DDIM) + i];

    // ---- phase 4: head outputs = h3 @ Wh + bh  K=200, N=304, 3 passes ----
    for (int p = 0; p < 3; p++) {
        int cb = p * 128 + tx * 4;
        if (cb < NHEADP) {
            float4 bias = *(const float4*)&g_bh[cb];
            float4 a0 = bias, a1 = bias, a2 = bias, a3 = bias;
#pragma unroll 4
            for (int k = 0; k < H3; k++) {
                float4 w = *(const float4*)&g_Wh[k * NHEADP + cb];
                float x;
                x = h3s[(r0 + 0) * S_H3 + k];
                a0.x = fmaf(x, w.x, a0.x); a0.y = fmaf(x, w.y, a0.y);
                a0.z = fmaf(x, w.z, a0.z); a0.w = fmaf(x, w.w, a0.w);
                x = h3s[(r0 + 1) * S_H3 + k];
                a1.x = fmaf(x, w.x, a1.x); a1.y = fmaf(x, w.y, a1.y);
                a1.z = fmaf(x, w.z, a1.z); a1.w = fmaf(x, w.w, a1.w);
                x = h3s[(r0 + 2) * S_H3 + k];
                a2.x = fmaf(x, w.x, a2.x); a2.y = fmaf(x, w.y, a2.y);
                a2.z = fmaf(x, w.z, a2.z); a2.w = fmaf(x, w.w, a2.w);
                x = h3s[(r0 + 3) * S_H3 + k];
                a3.x = fmaf(x, w.x, a3.x); a3.y = fmaf(x, w.y, a3.y);
                a3.z = fmaf(x, w.z, a3.z); a3.w = fmaf(x, w.w, a3.w);
            }
            *(float4*)&houts[(r0 + 0) * S_HO + cb] = a0;
            *(float4*)&houts[(r0 + 1) * S_HO + cb] = a1;
            *(float4*)&houts[(r0 + 2) * S_HO + cb] = a2;
            *(float4*)&houts[(r0 + 3) * S_HO + cb] = a3;
        }
    }
    __syncthreads();

    // ---- phase 5: Gumbel-argmax over G, select, emit ----
    if (t < ROWS * DDIM) {
        int r = t >> 2, d = t & 3;
        const float* ho = houts + r * S_HO;
        const float* gu = gums + r * (GCOMP * DDIM);
        float best = -CUDART_INF_F;
        int bi = 0;
#pragma unroll
        for (int g = 0; g < GCOMP; g++) {
            float pai = fabsf(ho[200 + g * 4 + d]);
            float sc = logf(pai + 1e-12f) + gu[g * 4 + d];
            if (sc > best) { best = sc; bi = g; }
        }
        float mu = ho[bi * 4 + d];
        float sg = fabsf(ho[100 + bi * 4 + d]);
        int gi = (row0 + r) * 4 + d;
        out[gi] = fmaf(randv[gi], sg, mu);
    }
}

// ---------------------------------------------------------------------------
// Launch
// inputs: 0:x0 1:rand 2:gumbel 3:W1 4:b1 5:W2 6:b2 7:W3 8:b3
//         9:Wmu 10:bmu 11:Wsig 12:bsig 13:Wpai 14:bpai
// ---------------------------------------------------------------------------
extern "C" void kernel_launch(void* const* d_in, const int* in_sizes, int n_in,
                              void* d_out, int out_size)
{
    const float* x0    = (const float*)d_in[0];
    const float* randv = (const float*)d_in[1];
    const float* gumb  = (const float*)d_in[2];
    const float* W1    = (const float*)d_in[3];
    const float* b1    = (const float*)d_in[4];
    const float* W2    = (const float*)d_in[5];
    const float* b2    = (const float*)d_in[6];
    const float* W3    = (const float*)d_in[7];
    const float* b3    = (const float*)d_in[8];
    const float* Wmu   = (const float*)d_in[9];
    const float* bmu   = (const float*)d_in[10];
    const float* Wsig  = (const float*)d_in[11];
    const float* bsig  = (const float*)d_in[12];
    const float* Wpai  = (const float*)d_in[13];
    const float* bpai  = (const float*)d_in[14];
    float* out = (float*)d_out;

    // opt-in to >48KB dynamic smem (host-side attribute set; capture-safe)
    cudaFuncSetAttribute(mdn_kernel,
                         cudaFuncAttributeMaxDynamicSharedMemorySize, SMEM_BYTES);

    // prep: transpose/pack weights (~147k elems)
    int prep_elems = H1 * H2 + H2 * H3P + H3 * NHEADP + NHEADP;
    int prep_blocks = (prep_elems + 255) / 256;
    prep_kernel<<<prep_blocks, 256>>>(W2, W3, Wmu, Wsig, Wpai, bmu, bsig, bpai);

    // main fused kernel
    int grid = BATCH / ROWS;   // 8192
    mdn_kernel<<<grid, THREADS, SMEM_BYTES>>>(x0, randv, gumb, W1, b1, b2, b3, out);
}

// round 5
// speedup vs baseline: 1.2476x; 1.2476x over previous
#include <cuda_runtime.h>
#include <math_constants.h>

// ---------------------------------------------------------------------------
// Problem constants
// ---------------------------------------------------------------------------
#define BATCH   262144
#define GCOMP   25
#define DDIM    4
#define H1      128
#define H2      256
#define H3      200
#define NHEAD   300          // 3 * G * D  (mu | sig | pai), order: head*100 + g*4 + d
#define NHEADP  304          // NHEAD padded

#define ROWS    32
#define THREADS 256

// ---------------------------------------------------------------------------
// Device scratch: transposed weights (k-major) + packed head bias
// ---------------------------------------------------------------------------
__device__ __align__(16) float g_W2t[H1 * H2];        // [k=128][c=256]
__device__ __align__(16) float g_W3t[H2 * H3];        // [k=256][c=200]
__device__ __align__(16) float g_Wh [H3 * NHEADP];    // [k=200][o=304] zero-padded
__device__ __align__(16) float g_bh [NHEADP];

// ---------------------------------------------------------------------------
// Prep kernel: build transposed weight layouts (~145k elems, once per launch)
// ---------------------------------------------------------------------------
__global__ void prep_kernel(const float* __restrict__ W2,
                            const float* __restrict__ W3,
                            const float* __restrict__ Wmu,
                            const float* __restrict__ Wsig,
                            const float* __restrict__ Wpai,
                            const float* __restrict__ bmu,
                            const float* __restrict__ bsig,
                            const float* __restrict__ bpai)
{
    const int t = blockIdx.x * blockDim.x + threadIdx.x;

    if (t < H1 * H2) {                       // W2t[k][c] = W2[c][k]
        int k = t / H2, c = t % H2;
        g_W2t[t] = W2[c * H1 + k];
    }
    {
        int t2 = t - H1 * H2;
        if (t2 >= 0 && t2 < H2 * H3) {       // W3t[k][c] = W3[c][k]
            int k = t2 / H3, c = t2 % H3;
            g_W3t[t2] = W3[c * H2 + k];
        }
    }
    {
        int t3 = t - H1 * H2 - H2 * H3;
        if (t3 >= 0 && t3 < H3 * NHEADP) {   // Wh[k][o], o = head*100 + (g*4+d)
            int k = t3 / NHEADP, o = t3 % NHEADP;
            float v = 0.f;
            if (o < NHEAD) {
                int h = o / 100, rem = o % 100;
                const float* W = (h == 0) ? Wmu : ((h == 1) ? Wsig : Wpai);
                v = W[rem * H3 + k];          // W shape (G,D,H3) flattened
            }
            g_Wh[t3] = v;
        }
    }
    {
        int t4 = t - H1 * H2 - H2 * H3 - H3 * NHEADP;
        if (t4 >= 0 && t4 < NHEADP) {
            float v = 0.f;
            if (t4 < NHEAD) {
                int h = t4 / 100, rem = t4 % 100;
                const float* bb = (h == 0) ? bmu : ((h == 1) ? bsig : bpai);
                v = bb[rem];
            }
            g_bh[t4] = v;
        }
    }
}

// ---------------------------------------------------------------------------
// SMEM layout (floats). hout reuses the h2+h1 region after phase 3.
// ---------------------------------------------------------------------------
#define S_H1 128
#define S_H2 260
#define S_H3 200
#define S_HO 304

#define O_H2    0                       // 32*260 = 8320
#define O_H1    8320                    // 32*128 = 4096  -> 12416
#define O_H3    12416                   // 32*200 = 6400  -> 18816
#define O_HOUT  0                       // 32*304 = 9728  (fits in 12416)
#define O_GUM   18816                   // 32*100 = 3200  -> 22016
#define O_X0    22016                   // 96             -> 22112
#define SMEM_FLOATS 22112
#define SMEM_BYTES  (SMEM_FLOATS * 4)   // 88448 B -> 2 blocks/SM, L1D ~51KB

__global__ __launch_bounds__(THREADS)
void mdn_kernel(const float* __restrict__ x0,
                const float* __restrict__ randv,
                const float* __restrict__ gumbel,
                const float* __restrict__ W1,
                const float* __restrict__ b1,
                const float* __restrict__ b2,
                const float* __restrict__ b3,
                float* __restrict__ out)
{
    extern __shared__ float sm[];
    float* h1s   = sm + O_H1;
    float* h2s   = sm + O_H2;
    float* h3s   = sm + O_H3;
    float* houts = sm + O_HOUT;
    float* gums  = sm + O_GUM;
    float* x0s   = sm + O_X0;

    const int t    = threadIdx.x;
    const int row0 = blockIdx.x * ROWS;

    // ---- phase 0: x0 tile ----
    if (t < ROWS * 3) x0s[t] = x0[row0 * 3 + t];
    __syncthreads();

    // ---- phase 1: h1 = relu(x0 @ W1^T + b1) ----
#pragma unroll
    for (int i = 0; i < (ROWS * H1) / THREADS; i++) {
        int o = t + i * THREADS;
        int r = o >> 7;
        int c = o & 127;
        float acc = b1[c];
        acc = fmaf(x0s[r * 3 + 0], W1[c * 3 + 0], acc);
        acc = fmaf(x0s[r * 3 + 1], W1[c * 3 + 1], acc);
        acc = fmaf(x0s[r * 3 + 2], W1[c * 3 + 2], acc);
        h1s[r * S_H1 + c] = fmaxf(acc, 0.f);
    }
    __syncthreads();

    const int ty = t >> 5;        // 0..7  -> row group of 4
    const int tx = t & 31;        // 0..31
    const int r0 = ty * 4;

    // ---- phase 2: h2 = relu(h1 @ W2^T + b2)  K=128, 256 cols, 8-col tiles ----
    {
        const int cb = tx * 8;
        float a[4][8];
        {
            float4 bb0 = *(const float4*)&b2[cb];
            float4 bb1 = *(const float4*)&b2[cb + 4];
#pragma unroll
            for (int i = 0; i < 4; i++) {
                a[i][0]=bb0.x; a[i][1]=bb0.y; a[i][2]=bb0.z; a[i][3]=bb0.w;
                a[i][4]=bb1.x; a[i][5]=bb1.y; a[i][6]=bb1.z; a[i][7]=bb1.w;
            }
        }
#pragma unroll 2
        for (int k = 0; k < H1; k += 4) {
            float4 xv[4];
#pragma unroll
            for (int i = 0; i < 4; i++)
                xv[i] = *(const float4*)&h1s[(r0 + i) * S_H1 + k];
#pragma unroll
            for (int j = 0; j < 4; j++) {
                float4 w0 = *(const float4*)&g_W2t[(k + j) * H2 + cb];
                float4 w1 = *(const float4*)&g_W2t[(k + j) * H2 + cb + 4];
#pragma unroll
                for (int i = 0; i < 4; i++) {
                    float x = ((const float*)&xv[i])[j];
                    a[i][0] = fmaf(x, w0.x, a[i][0]);
                    a[i][1] = fmaf(x, w0.y, a[i][1]);
                    a[i][2] = fmaf(x, w0.z, a[i][2]);
                    a[i][3] = fmaf(x, w0.w, a[i][3]);
                    a[i][4] = fmaf(x, w1.x, a[i][4]);
                    a[i][5] = fmaf(x, w1.y, a[i][5]);
                    a[i][6] = fmaf(x, w1.z, a[i][6]);
                    a[i][7] = fmaf(x, w1.w, a[i][7]);
                }
            }
        }
#pragma unroll
        for (int i = 0; i < 4; i++) {
            float4 s0, s1;
            s0.x = fmaxf(a[i][0], 0.f); s0.y = fmaxf(a[i][1], 0.f);
            s0.z = fmaxf(a[i][2], 0.f); s0.w = fmaxf(a[i][3], 0.f);
            s1.x = fmaxf(a[i][4], 0.f); s1.y = fmaxf(a[i][5], 0.f);
            s1.z = fmaxf(a[i][6], 0.f); s1.w = fmaxf(a[i][7], 0.f);
            *(float4*)&h2s[(r0 + i) * S_H2 + cb]     = s0;
            *(float4*)&h2s[(r0 + i) * S_H2 + cb + 4] = s1;
        }
    }
    __syncthreads();

    // ---- phase 3: h3 = relu(h2 @ W3^T + b3)  K=256, 200 cols, 8-col tiles ----
    {
        const int cb = tx * 8;
        if (cb < H3) {                       // tx < 25 active
            float a[4][8];
            {
                float4 bb0 = *(const float4*)&b3[cb];
                float4 bb1 = *(const float4*)&b3[cb + 4];
#pragma unroll
                for (int i = 0; i < 4; i++) {
                    a[i][0]=bb0.x; a[i][1]=bb0.y; a[i][2]=bb0.z; a[i][3]=bb0.w;
                    a[i][4]=bb1.x; a[i][5]=bb1.y; a[i][6]=bb1.z; a[i][7]=bb1.w;
                }
            }
#pragma unroll 2
            for (int k = 0; k < H2; k += 4) {
                float4 xv[4];
#pragma unroll
                for (int i = 0; i < 4; i++)
                    xv[i] = *(const float4*)&h2s[(r0 + i) * S_H2 + k];
#pragma unroll
                for (int j = 0; j < 4; j++) {
                    float4 w0 = *(const float4*)&g_W3t[(k + j) * H3 + cb];
                    float4 w1 = *(const float4*)&g_W3t[(k + j) * H3 + cb + 4];
#pragma unroll
                    for (int i = 0; i < 4; i++) {
                        float x = ((const float*)&xv[i])[j];
                        a[i][0] = fmaf(x, w0.x, a[i][0]);
                        a[i][1] = fmaf(x, w0.y, a[i][1]);
                        a[i][2] = fmaf(x, w0.z, a[i][2]);
                        a[i][3] = fmaf(x, w0.w, a[i][3]);
                        a[i][4] = fmaf(x, w1.x, a[i][4]);
                        a[i][5] = fmaf(x, w1.y, a[i][5]);
                        a[i][6] = fmaf(x, w1.z, a[i][6]);
                        a[i][7] = fmaf(x, w1.w, a[i][7]);
                    }
                }
            }
#pragma unroll
            for (int i = 0; i < 4; i++) {
                float4 s0, s1;
                s0.x = fmaxf(a[i][0], 0.f); s0.y = fmaxf(a[i][1], 0.f);
                s0.z = fmaxf(a[i][2], 0.f); s0.w = fmaxf(a[i][3], 0.f);
                s1.x = fmaxf(a[i][4], 0.f); s1.y = fmaxf(a[i][5], 0.f);
                s1.z = fmaxf(a[i][6], 0.f); s1.w = fmaxf(a[i][7], 0.f);
                *(float4*)&h3s[(r0 + i) * S_H3 + cb]     = s0;
                *(float4*)&h3s[(r0 + i) * S_H3 + cb + 4] = s1;
            }
        }
    }
    __syncthreads();

    // ---- gumbel tile load (coalesced) ----
    for (int i = t; i < ROWS * GCOMP * DDIM; i += THREADS)
        gums[i] = gumbel[row0 * (GCOMP * DDIM) + i];

    // ---- phase 4: heads = h3 @ Wh + bh  K=200, 304 cols, 4-col x 3 passes ----
    for (int p = 0; p < 3; p++) {
        int cb = p * 128 + tx * 4;
        if (cb < NHEADP) {
            float4 bias = *(const float4*)&g_bh[cb];
            float a0 = bias.x, a1 = bias.y, a2 = bias.z, a3 = bias.w;
            float b0 = bias.x, b1v = bias.y, b2v = bias.z, b3v = bias.w;
            float c0 = bias.x, c1 = bias.y, c2 = bias.z, c3 = bias.w;
            float d0 = bias.x, d1 = bias.y, d2 = bias.z, d3 = bias.w;
#pragma unroll 2
            for (int k = 0; k < H3; k += 4) {
                float4 xv0 = *(const float4*)&h3s[(r0 + 0) * S_H3 + k];
                float4 xv1 = *(const float4*)&h3s[(r0 + 1) * S_H3 + k];
                float4 xv2 = *(const float4*)&h3s[(r0 + 2) * S_H3 + k];
                float4 xv3 = *(const float4*)&h3s[(r0 + 3) * S_H3 + k];
#pragma unroll
                for (int j = 0; j < 4; j++) {
                    float4 w = *(const float4*)&g_Wh[(k + j) * NHEADP + cb];
                    float x0v = ((const float*)&xv0)[j];
                    float x1v = ((const float*)&xv1)[j];
                    float x2v = ((const float*)&xv2)[j];
                    float x3v = ((const float*)&xv3)[j];
                    a0 = fmaf(x0v, w.x, a0); a1 = fmaf(x0v, w.y, a1);
                    a2 = fmaf(x0v, w.z, a2); a3 = fmaf(x0v, w.w, a3);
                    b0 = fmaf(x1v, w.x, b0); b1v = fmaf(x1v, w.y, b1v);
                    b2v = fmaf(x1v, w.z, b2v); b3v = fmaf(x1v, w.w, b3v);
                    c0 = fmaf(x2v, w.x, c0); c1 = fmaf(x2v, w.y, c1);
                    c2 = fmaf(x2v, w.z, c2); c3 = fmaf(x2v, w.w, c3);
                    d0 = fmaf(x3v, w.x, d0); d1 = fmaf(x3v, w.y, d1);
                    d2 = fmaf(x3v, w.z, d2); d3 = fmaf(x3v, w.w, d3);
                }
            }
            *(float4*)&houts[(r0 + 0) * S_HO + cb] = make_float4(a0, a1, a2, a3);
            *(float4*)&houts[(r0 + 1) * S_HO + cb] = make_float4(b0, b1v, b2v, b3v);
            *(float4*)&houts[(r0 + 2) * S_HO + cb] = make_float4(c0, c1, c2, c3);
            *(float4*)&houts[(r0 + 3) * S_HO + cb] = make_float4(d0, d1, d2, d3);
        }
    }
    __syncthreads();

    // ---- phase 5: Gumbel-argmax over G, select, emit ----
    if (t < ROWS * DDIM) {
        int r = t >> 2, d = t & 3;
        const float* ho = houts + r * S_HO;
        const float* gu = gums + r * (GCOMP * DDIM);
        float best = -CUDART_INF_F;
        int bi = 0;
#pragma unroll
        for (int g = 0; g < GCOMP; g++) {
            float pai = fabsf(ho[200 + g * 4 + d]);
            float sc = logf(pai + 1e-12f) + gu[g * 4 + d];
            if (sc > best) { best = sc; bi = g; }
        }
        float mu = ho[bi * 4 + d];
        float sg = fabsf(ho[100 + bi * 4 + d]);
        int gi = (row0 + r) * 4 + d;
        out[gi] = fmaf(randv[gi], sg, mu);
    }
}

// ---------------------------------------------------------------------------
// Launch
// inputs: 0:x0 1:rand 2:gumbel 3:W1 4:b1 5:W2 6:b2 7:W3 8:b3
//         9:Wmu 10:bmu 11:Wsig 12:bsig 13:Wpai 14:bpai
// ---------------------------------------------------------------------------
extern "C" void kernel_launch(void* const* d_in, const int* in_sizes, int n_in,
                              void* d_out, int out_size)
{
    const float* x0    = (const float*)d_in[0];
    const float* randv = (const float*)d_in[1];
    const float* gumb  = (const float*)d_in[2];
    const float* W1    = (const float*)d_in[3];
    const float* b1    = (const float*)d_in[4];
    const float* W2    = (const float*)d_in[5];
    const float* b2    = (const float*)d_in[6];
    const float* W3    = (const float*)d_in[7];
    const float* b3    = (const float*)d_in[8];
    const float* Wmu   = (const float*)d_in[9];
    const float* bmu   = (const float*)d_in[10];
    const float* Wsig  = (const float*)d_in[11];
    const float* bsig  = (const float*)d_in[12];
    const float* Wpai  = (const float*)d_in[13];
    const float* bpai  = (const float*)d_in[14];
    float* out = (float*)d_out;

    cudaFuncSetAttribute(mdn_kernel,
                         cudaFuncAttributeMaxDynamicSharedMemorySize, SMEM_BYTES);

    int prep_elems = H1 * H2 + H2 * H3 + H3 * NHEADP + NHEADP;
    int prep_blocks = (prep_elems + 255) / 256;
    prep_kernel<<<prep_blocks, 256>>>(W2, W3, Wmu, Wsig, Wpai, bmu, bsig, bpai);

    int grid = BATCH / ROWS;   // 8192
    mdn_kernel<<<grid, THREADS, SMEM_BYTES>>>(x0, randv, gumb, W1, b1, b2, b3, out);
}

// round 6
// speedup vs baseline: 1.2483x; 1.0006x over previous
#include <cuda_runtime.h>
#include <math_constants.h>

// ---------------------------------------------------------------------------
// Problem constants
// ---------------------------------------------------------------------------
#define BATCH   262144
#define GCOMP   25
#define DDIM    4
#define H1      128
#define H2      256
#define H3      200
#define NHEAD   300          // 3 * G * D  (mu | sig | pai), order: head*100 + g*4 + d
#define NHEADP  304          // NHEAD padded

#define ROWS    32
#define THREADS 256

// ---------------------------------------------------------------------------
// Device scratch: transposed weights (k-major) + packed head bias
// ---------------------------------------------------------------------------
__device__ __align__(16) float g_W2t[H1 * H2];        // [k=128][c=256]
__device__ __align__(16) float g_W3t[H2 * H3];        // [k=256][c=200]
__device__ __align__(16) float g_Wh [H3 * NHEADP];    // [k=200][o=304] zero-padded
__device__ __align__(16) float g_bh [NHEADP];

// ---------------------------------------------------------------------------
// Prep kernel: build transposed weight layouts (~145k elems, once per launch)
// ---------------------------------------------------------------------------
__global__ void prep_kernel(const float* __restrict__ W2,
                            const float* __restrict__ W3,
                            const float* __restrict__ Wmu,
                            const float* __restrict__ Wsig,
                            const float* __restrict__ Wpai,
                            const float* __restrict__ bmu,
                            const float* __restrict__ bsig,
                            const float* __restrict__ bpai)
{
    const int t = blockIdx.x * blockDim.x + threadIdx.x;

    if (t < H1 * H2) {                       // W2t[k][c] = W2[c][k]
        int k = t / H2, c = t % H2;
        g_W2t[t] = W2[c * H1 + k];
    }
    {
        int t2 = t - H1 * H2;
        if (t2 >= 0 && t2 < H2 * H3) {       // W3t[k][c] = W3[c][k]
            int k = t2 / H3, c = t2 % H3;
            g_W3t[t2] = W3[c * H2 + k];
        }
    }
    {
        int t3 = t - H1 * H2 - H2 * H3;
        if (t3 >= 0 && t3 < H3 * NHEADP) {   // Wh[k][o], o = head*100 + (g*4+d)
            int k = t3 / NHEADP, o = t3 % NHEADP;
            float v = 0.f;
            if (o < NHEAD) {
                int h = o / 100, rem = o % 100;
                const float* W = (h == 0) ? Wmu : ((h == 1) ? Wsig : Wpai);
                v = W[rem * H3 + k];          // W shape (G,D,H3) flattened
            }
            g_Wh[t3] = v;
        }
    }
    {
        int t4 = t - H1 * H2 - H2 * H3 - H3 * NHEADP;
        if (t4 >= 0 && t4 < NHEADP) {
            float v = 0.f;
            if (t4 < NHEAD) {
                int h = t4 / 100, rem = t4 % 100;
                const float* bb = (h == 0) ? bmu : ((h == 1) ? bsig : bpai);
                v = bb[rem];
            }
            g_bh[t4] = v;
        }
    }
}

// ---------------------------------------------------------------------------
// SMEM layout (floats). hout reuses the h2+h1 region after phase 3.
// ---------------------------------------------------------------------------
#define S_H1 128
#define S_H2 260
#define S_H3 200
#define S_HO 304

#define O_H2    0                       // 32*260 = 8320
#define O_H1    8320                    // 32*128 = 4096  -> 12416
#define O_H3    12416                   // 32*200 = 6400  -> 18816
#define O_HOUT  0                       // 32*304 = 9728  (fits in 12416)
#define O_GUM   18816                   // 32*100 = 3200  -> 22016
#define O_X0    22016                   // 96             -> 22112
#define SMEM_FLOATS 22112
#define SMEM_BYTES  (SMEM_FLOATS * 4)   // 88448 B -> 2 blocks/SM, L1D ~51KB

__global__ __launch_bounds__(THREADS)
void mdn_kernel(const float* __restrict__ x0,
                const float* __restrict__ randv,
                const float* __restrict__ gumbel,
                const float* __restrict__ W1,
                const float* __restrict__ b1,
                const float* __restrict__ b2,
                const float* __restrict__ b3,
                float* __restrict__ out)
{
    extern __shared__ float sm[];
    float* h1s   = sm + O_H1;
    float* h2s   = sm + O_H2;
    float* h3s   = sm + O_H3;
    float* houts = sm + O_HOUT;
    float* gums  = sm + O_GUM;
    float* x0s   = sm + O_X0;

    const int t    = threadIdx.x;
    const int row0 = blockIdx.x * ROWS;

    // ---- phase 0: x0 tile ----
    if (t < ROWS * 3) x0s[t] = x0[row0 * 3 + t];
    __syncthreads();

    // ---- phase 1: h1 = relu(x0 @ W1^T + b1) ----
#pragma unroll
    for (int i = 0; i < (ROWS * H1) / THREADS; i++) {
        int o = t + i * THREADS;
        int r = o >> 7;
        int c = o & 127;
        float acc = b1[c];
        acc = fmaf(x0s[r * 3 + 0], W1[c * 3 + 0], acc);
        acc = fmaf(x0s[r * 3 + 1], W1[c * 3 + 1], acc);
        acc = fmaf(x0s[r * 3 + 2], W1[c * 3 + 2], acc);
        h1s[r * S_H1 + c] = fmaxf(acc, 0.f);
    }
    __syncthreads();

    const int ty = t >> 5;        // 0..7  -> row group of 4
    const int tx = t & 31;        // 0..31
    const int r0 = ty * 4;

    // ---- phase 2: h2 = relu(h1 @ W2^T + b2)  K=128, 256 cols, 8-col tiles ----
    {
        const int cb = tx * 8;
        float a[4][8];
        {
            float4 bb0 = *(const float4*)&b2[cb];
            float4 bb1 = *(const float4*)&b2[cb + 4];
#pragma unroll
            for (int i = 0; i < 4; i++) {
                a[i][0]=bb0.x; a[i][1]=bb0.y; a[i][2]=bb0.z; a[i][3]=bb0.w;
                a[i][4]=bb1.x; a[i][5]=bb1.y; a[i][6]=bb1.z; a[i][7]=bb1.w;
            }
        }
#pragma unroll 2
        for (int k = 0; k < H1; k += 4) {
            float4 xv[4];
#pragma unroll
            for (int i = 0; i < 4; i++)
                xv[i] = *(const float4*)&h1s[(r0 + i) * S_H1 + k];
#pragma unroll
            for (int j = 0; j < 4; j++) {
                float4 w0 = *(const float4*)&g_W2t[(k + j) * H2 + cb];
                float4 w1 = *(const float4*)&g_W2t[(k + j) * H2 + cb + 4];
#pragma unroll
                for (int i = 0; i < 4; i++) {
                    float x = ((const float*)&xv[i])[j];
                    a[i][0] = fmaf(x, w0.x, a[i][0]);
                    a[i][1] = fmaf(x, w0.y, a[i][1]);
                    a[i][2] = fmaf(x, w0.z, a[i][2]);
                    a[i][3] = fmaf(x, w0.w, a[i][3]);
                    a[i][4] = fmaf(x, w1.x, a[i][4]);
                    a[i][5] = fmaf(x, w1.y, a[i][5]);
                    a[i][6] = fmaf(x, w1.z, a[i][6]);
                    a[i][7] = fmaf(x, w1.w, a[i][7]);
                }
            }
        }
#pragma unroll
        for (int i = 0; i < 4; i++) {
            float4 s0, s1;
            s0.x = fmaxf(a[i][0], 0.f); s0.y = fmaxf(a[i][1], 0.f);
            s0.z = fmaxf(a[i][2], 0.f); s0.w = fmaxf(a[i][3], 0.f);
            s1.x = fmaxf(a[i][4], 0.f); s1.y = fmaxf(a[i][5], 0.f);
            s1.z = fmaxf(a[i][6], 0.f); s1.w = fmaxf(a[i][7], 0.f);
            *(float4*)&h2s[(r0 + i) * S_H2 + cb]     = s0;
            *(float4*)&h2s[(r0 + i) * S_H2 + cb + 4] = s1;
        }
    }
    __syncthreads();

    // ---- phase 3: h3 = relu(h2 @ W3^T + b3)  K=256, 200 cols, 8-col tiles ----
    {
        const int cb = tx * 8;
        if (cb < H3) {                       // tx < 25 active
            float a[4][8];
            {
                float4 bb0 = *(const float4*)&b3[cb];
                float4 bb1 = *(const float4*)&b3[cb + 4];
#pragma unroll
                for (int i = 0; i < 4; i++) {
                    a[i][0]=bb0.x; a[i][1]=bb0.y; a[i][2]=bb0.z; a[i][3]=bb0.w;
                    a[i][4]=bb1.x; a[i][5]=bb1.y; a[i][6]=bb1.z; a[i][7]=bb1.w;
                }
            }
#pragma unroll 2
            for (int k = 0; k < H2; k += 4) {
                float4 xv[4];
#pragma unroll
                for (int i = 0; i < 4; i++)
                    xv[i] = *(const float4*)&h2s[(r0 + i) * S_H2 + k];
#pragma unroll
                for (int j = 0; j < 4; j++) {
                    float4 w0 = *(const float4*)&g_W3t[(k + j) * H3 + cb];
                    float4 w1 = *(const float4*)&g_W3t[(k + j) * H3 + cb + 4];
#pragma unroll
                    for (int i = 0; i < 4; i++) {
                        float x = ((const float*)&xv[i])[j];
                        a[i][0] = fmaf(x, w0.x, a[i][0]);
                        a[i][1] = fmaf(x, w0.y, a[i][1]);
                        a[i][2] = fmaf(x, w0.z, a[i][2]);
                        a[i][3] = fmaf(x, w0.w, a[i][3]);
                        a[i][4] = fmaf(x, w1.x, a[i][4]);
                        a[i][5] = fmaf(x, w1.y, a[i][5]);
                        a[i][6] = fmaf(x, w1.z, a[i][6]);
                        a[i][7] = fmaf(x, w1.w, a[i][7]);
                    }
                }
            }
#pragma unroll
            for (int i = 0; i < 4; i++) {
                float4 s0, s1;
                s0.x = fmaxf(a[i][0], 0.f); s0.y = fmaxf(a[i][1], 0.f);
                s0.z = fmaxf(a[i][2], 0.f); s0.w = fmaxf(a[i][3], 0.f);
                s1.x = fmaxf(a[i][4], 0.f); s1.y = fmaxf(a[i][5], 0.f);
                s1.z = fmaxf(a[i][6], 0.f); s1.w = fmaxf(a[i][7], 0.f);
                *(float4*)&h3s[(r0 + i) * S_H3 + cb]     = s0;
                *(float4*)&h3s[(r0 + i) * S_H3 + cb + 4] = s1;
            }
        }
    }
    __syncthreads();

    // ---- gumbel tile load (coalesced) ----
    for (int i = t; i < ROWS * GCOMP * DDIM; i += THREADS)
        gums[i] = gumbel[row0 * (GCOMP * DDIM) + i];

    // ---- phase 4: heads = h3 @ Wh + bh  K=200, 304 cols, 4-col x 3 passes ----
    for (int p = 0; p < 3; p++) {
        int cb = p * 128 + tx * 4;
        if (cb < NHEADP) {
            float4 bias = *(const float4*)&g_bh[cb];
            float a0 = bias.x, a1 = bias.y, a2 = bias.z, a3 = bias.w;
            float b0 = bias.x, b1v = bias.y, b2v = bias.z, b3v = bias.w;
            float c0 = bias.x, c1 = bias.y, c2 = bias.z, c3 = bias.w;
            float d0 = bias.x, d1 = bias.y, d2 = bias.z, d3 = bias.w;
#pragma unroll 2
            for (int k = 0; k < H3; k += 4) {
                float4 xv0 = *(const float4*)&h3s[(r0 + 0) * S_H3 + k];
                float4 xv1 = *(const float4*)&h3s[(r0 + 1) * S_H3 + k];
                float4 xv2 = *(const float4*)&h3s[(r0 + 2) * S_H3 + k];
                float4 xv3 = *(const float4*)&h3s[(r0 + 3) * S_H3 + k];
#pragma unroll
                for (int j = 0; j < 4; j++) {
                    float4 w = *(const float4*)&g_Wh[(k + j) * NHEADP + cb];
                    float x0v = ((const float*)&xv0)[j];
                    float x1v = ((const float*)&xv1)[j];
                    float x2v = ((const float*)&xv2)[j];
                    float x3v = ((const float*)&xv3)[j];
                    a0 = fmaf(x0v, w.x, a0); a1 = fmaf(x0v, w.y, a1);
                    a2 = fmaf(x0v, w.z, a2); a3 = fmaf(x0v, w.w, a3);
                    b0 = fmaf(x1v, w.x, b0); b1v = fmaf(x1v, w.y, b1v);
                    b2v = fmaf(x1v, w.z, b2v); b3v = fmaf(x1v, w.w, b3v);
                    c0 = fmaf(x2v, w.x, c0); c1 = fmaf(x2v, w.y, c1);
                    c2 = fmaf(x2v, w.z, c2); c3 = fmaf(x2v, w.w, c3);
                    d0 = fmaf(x3v, w.x, d0); d1 = fmaf(x3v, w.y, d1);
                    d2 = fmaf(x3v, w.z, d2); d3 = fmaf(x3v, w.w, d3);
                }
            }
            *(float4*)&houts[(r0 + 0) * S_HO + cb] = make_float4(a0, a1, a2, a3);
            *(float4*)&houts[(r0 + 1) * S_HO + cb] = make_float4(b0, b1v, b2v, b3v);
            *(float4*)&houts[(r0 + 2) * S_HO + cb] = make_float4(c0, c1, c2, c3);
            *(float4*)&houts[(r0 + 3) * S_HO + cb] = make_float4(d0, d1, d2, d3);
        }
    }
    __syncthreads();

    // ---- phase 5: Gumbel-argmax over G, select, emit ----
    if (t < ROWS * DDIM) {
        int r = t >> 2, d = t & 3;
        const float* ho = houts + r * S_HO;
        const float* gu = gums + r * (GCOMP * DDIM);
        float best = -CUDART_INF_F;
        int bi = 0;
#pragma unroll
        for (int g = 0; g < GCOMP; g++) {
            float pai = fabsf(ho[200 + g * 4 + d]);
            float sc = logf(pai + 1e-12f) + gu[g * 4 + d];
            if (sc > best) { best = sc; bi = g; }
        }
        float mu = ho[bi * 4 + d];
        float sg = fabsf(ho[100 + bi * 4 + d]);
        int gi = (row0 + r) * 4 + d;
        out[gi] = fmaf(randv[gi], sg, mu);
    }
}

// ---------------------------------------------------------------------------
// Launch
// inputs: 0:x0 1:rand 2:gumbel 3:W1 4:b1 5:W2 6:b2 7:W3 8:b3
//         9:Wmu 10:bmu 11:Wsig 12:bsig 13:Wpai 14:bpai
// ---------------------------------------------------------------------------
extern "C" void kernel_launch(void* const* d_in, const int* in_sizes, int n_in,
                              void* d_out, int out_size)
{
    const float* x0    = (const float*)d_in[0];
    const float* randv = (const float*)d_in[1];
    const float* gumb  = (const float*)d_in[2];
    const float* W1    = (const float*)d_in[3];
    const float* b1    = (const float*)d_in[4];
    const float* W2    = (const float*)d_in[5];
    const float* b2    = (const float*)d_in[6];
    const float* W3    = (const float*)d_in[7];
    const float* b3    = (const float*)d_in[8];
    const float* Wmu   = (const float*)d_in[9];
    const float* bmu   = (const float*)d_in[10];
    const float* Wsig  = (const float*)d_in[11];
    const float* bsig  = (const float*)d_in[12];
    const float* Wpai  = (const float*)d_in[13];
    const float* bpai  = (const float*)d_in[14];
    float* out = (float*)d_out;

    cudaFuncSetAttribute(mdn_kernel,
                         cudaFuncAttributeMaxDynamicSharedMemorySize, SMEM_BYTES);

    int prep_elems = H1 * H2 + H2 * H3 + H3 * NHEADP + NHEADP;
    int prep_blocks = (prep_elems + 255) / 256;
    prep_kernel<<<prep_blocks, 256>>>(W2, W3, Wmu, Wsig, Wpai, bmu, bsig, bpai);

    int grid = BATCH / ROWS;   // 8192
    mdn_kernel<<<grid, THREADS, SMEM_BYTES>>>(x0, randv, gumb, W1, b1, b2, b3, out);
}

// round 8
// speedup vs baseline: 1.5361x; 1.2305x over previous
#include <cuda_runtime.h>
#include <math_constants.h>

#define BATCH   262144
#define GCOMP   25
#define DDIM    4
#define H1      128
#define H2      256
#define H3      200
#define NHEAD   300
#define H3P     224
#define NHEADP  320

#define ROWS    32
#define THREADS 256

// ---- packed f32x2 helpers ----
__device__ __forceinline__ void ffma2(unsigned long long& a,
                                      unsigned long long x,
                                      unsigned long long w) {
    asm("fma.rn.f32x2 %0, %1, %2, %0;" : "+l"(a) : "l"(x), "l"(w));
}
__device__ __forceinline__ unsigned long long pack2(float lo, float hi) {
    unsigned long long r;
    asm("mov.b64 %0, {%1, %2};" : "=l"(r) : "f"(lo), "f"(hi));
    return r;
}
__device__ __forceinline__ float2 unpack2(unsigned long long a) {
    float2 f;
    asm("mov.b64 {%0, %1}, %2;" : "=f"(f.x), "=f"(f.y) : "l"(a));
    return f;
}

// ---- k-pair-major packed weights: gWp[kp][c][j] = W[c][2kp+j] ----
__device__ __align__(16) float g_W2p[(H1 / 2) * H2 * 2];
__device__ __align__(16) float g_W3p[(H2 / 2) * H3P * 2];
__device__ __align__(16) float g_Whp[(H3 / 2) * NHEADP * 2];
__device__ __align__(16) float g_b3p[H3P];
__device__ __align__(16) float g_bh [NHEADP];

__global__ void prep_kernel(const float* __restrict__ W2,
                            const float* __restrict__ W3,
                            const float* __restrict__ Wmu,
                            const float* __restrict__ Wsig,
                            const float* __restrict__ Wpai,
                            const float* __restrict__ b3,
                            const float* __restrict__ bmu,
                            const float* __restrict__ bsig,
                            const float* __restrict__ bpai)
{
    const int t = blockIdx.x * blockDim.x + threadIdx.x;
    const int N2 = (H1 / 2) * H2 * 2;
    const int N3 = (H2 / 2) * H3P * 2;
    const int Nh = (H3 / 2) * NHEADP * 2;

    if (t < N2) {
        int kp = t / (H2 * 2), r = t % (H2 * 2);
        int c = r >> 1, j = r & 1;
        g_W2p[t] = W2[c * H1 + 2 * kp + j];
    }
    {
        int t2 = t - N2;
        if (t2 >= 0 && t2 < N3) {
            int kp = t2 / (H3P * 2), r = t2 % (H3P * 2);
            int c = r >> 1, j = r & 1;
            g_W3p[t2] = (c < H3) ? W3[c * H2 + 2 * kp + j] : 0.f;
        }
    }
    {
        int t3 = t - N2 - N3;
        if (t3 >= 0 && t3 < Nh) {
            int kp = t3 / (NHEADP * 2), r = t3 % (NHEADP * 2);
            int o = r >> 1, j = r & 1;
            float v = 0.f;
            if (o < NHEAD) {
                int h = o / 100, rem = o % 100;
                const float* W = (h == 0) ? Wmu : ((h == 1) ? Wsig : Wpai);
                v = W[rem * H3 + 2 * kp + j];
            }
            g_Whp[t3] = v;
        }
    }
    {
        int t4 = t - N2 - N3 - Nh;
        if (t4 >= 0 && t4 < H3P)
            g_b3p[t4] = (t4 < H3) ? b3[t4] : 0.f;
    }
    {
        int t5 = t - N2 - N3 - Nh - H3P;
        if (t5 >= 0 && t5 < NHEADP) {
            float v = 0.f;
            if (t5 < NHEAD) {
                int h = t5 / 100, rem = t5 % 100;
                const float* bb = (h == 0) ? bmu : ((h == 1) ? bsig : bpai);
                v = bb[rem];
            }
            g_bh[t5] = v;
        }
    }
}

// ---- SMEM layout. Activations stored with quad XOR swizzle:
//      logical col c of row r lives at c ^ (4*((r>>3)&1)). ----
#define S_H1 128
#define S_H2 256
#define S_H3 224
#define S_HO 320

#define O_H2    0                       // 32*256 = 8192
#define O_H1    8192                    // 32*128 = 4096 -> 12288
#define O_H3    12288                   // 32*224 = 7168 -> 19456
#define O_HOUT  0                       // 32*320 = 10240 (inside 12288)
#define O_GUM   19456                   // 3200 -> 22656
#define O_X0    22656                   // 96   -> 22752
#define SMEM_FLOATS 22752
#define SMEM_BYTES  (SMEM_FLOATS * 4)   // 91008 B -> 2 blocks/SM

// One 16x32 unit: lane = 8 rows x 2 cols, k-pair FFMA2 accumulation.
template<int K, int SA, int CT>
__device__ __forceinline__ void gemm32(const float* __restrict__ act_r0,
                                       int half,
                                       const float* __restrict__ wp,
                                       int cb,
                                       unsigned long long (&acc)[8][2])
{
    const float* pE = act_r0 + half * (8 * SA + 4);       // logical even quads
    const float* pO = act_r0 + half * (8 * SA - 4) + 4;   // logical odd quads
    const float* wb = wp + cb * 2;

#pragma unroll 2
    for (int c8 = 0; c8 < K / 8; c8++) {
        const float* w = wb + (4 * c8) * (CT * 2);
        ulonglong2 w0 = *(const ulonglong2*)(w);
        ulonglong2 w1 = *(const ulonglong2*)(w + CT * 2);
        ulonglong2 w2 = *(const ulonglong2*)(w + CT * 4);
        ulonglong2 w3 = *(const ulonglong2*)(w + CT * 6);
#pragma unroll
        for (int i = 0; i < 8; i++) {
            ulonglong2 xe = *(const ulonglong2*)(pE + i * SA + c8 * 8);
            ulonglong2 xo = *(const ulonglong2*)(pO + i * SA + c8 * 8);
            ffma2(acc[i][0], xe.x, w0.x); ffma2(acc[i][1], xe.x, w0.y);
            ffma2(acc[i][0], xe.y, w1.x); ffma2(acc[i][1], xe.y, w1.y);
            ffma2(acc[i][0], xo.x, w2.x); ffma2(acc[i][1], xo.x, w2.y);
            ffma2(acc[i][0], xo.y, w3.x); ffma2(acc[i][1], xo.y, w3.y);
        }
    }
}

__global__ __launch_bounds__(THREADS)
void mdn_kernel(const float* __restrict__ x0,
                const float* __restrict__ randv,
                const float* __restrict__ gumbel,
                const float* __restrict__ W1,
                const float* __restrict__ b1,
                const float* __restrict__ b2,
                float* __restrict__ out)
{
    extern __shared__ float sm[];
    float* h1s   = sm + O_H1;
    float* h2s   = sm + O_H2;
    float* h3s   = sm + O_H3;
    float* houts = sm + O_HOUT;
    float* gums  = sm + O_GUM;
    float* x0s   = sm + O_X0;

    const int t    = threadIdx.x;
    const int w    = t >> 5;
    const int lane = t & 31;
    const int half = lane >> 4;
    const int slot = lane & 15;
    const int row0 = blockIdx.x * ROWS;

    if (t < ROWS * 3) x0s[t] = x0[row0 * 3 + t];
    __syncthreads();

    // phase 1: h1 = relu(x0 @ W1^T + b1), swizzled store
#pragma unroll
    for (int i = 0; i < (ROWS * H1) / THREADS; i++) {
        int o = t + i * THREADS;
        int r = o >> 7;
        int c = o & 127;
        float acc1 = b1[c];
        acc1 = fmaf(x0s[r * 3 + 0], W1[c * 3 + 0], acc1);
        acc1 = fmaf(x0s[r * 3 + 1], W1[c * 3 + 1], acc1);
        acc1 = fmaf(x0s[r * 3 + 2], W1[c * 3 + 2], acc1);
        int cs = c ^ ((((unsigned)r >> 3) & 1) << 2);
        h1s[r * S_H1 + cs] = fmaxf(acc1, 0.f);
    }
    __syncthreads();

    unsigned long long acc[8][2];

    // phase 2: K=128, 256 cols, 16 units
    for (int u = w; u < 16; u += 8) {
        int r0 = (u & 1) * 16;
        int cb = (u >> 1) * 32 + slot * 2;
        unsigned long long bi0 = pack2(b2[cb], 0.f);
        unsigned long long bi1 = pack2(b2[cb + 1], 0.f);
#pragma unroll
        for (int i = 0; i < 8; i++) { acc[i][0] = bi0; acc[i][1] = bi1; }
        gemm32<H1, S_H1, H2>(h1s + r0 * S_H1, half, g_W2p, cb, acc);
        int cs = cb ^ (half << 2);
#pragma unroll
        for (int i = 0; i < 8; i++) {
            int r = r0 + half * 8 + i;
            float2 p0 = unpack2(acc[i][0]);
            float2 p1 = unpack2(acc[i][1]);
            *(float2*)&h2s[r * S_H2 + cs] =
                make_float2(fmaxf(p0.x + p0.y, 0.f), fmaxf(p1.x + p1.y, 0.f));
        }
    }
    __syncthreads();

    // phase 3: K=256, 224 cols (200 real), 14 units
    for (int u = w; u < 14; u += 8) {
        int r0 = (u & 1) * 16;
        int cb = (u >> 1) * 32 + slot * 2;
        unsigned long long bi0 = pack2(g_b3p[cb], 0.f);
        unsigned long long bi1 = pack2(g_b3p[cb + 1], 0.f);
#pragma unroll
        for (int i = 0; i < 8; i++) { acc[i][0] = bi0; acc[i][1] = bi1; }
        gemm32<H2, S_H2, H3P>(h2s + r0 * S_H2, half, g_W3p, cb, acc);
        if (cb < H3) {
            int cs = cb ^ (half << 2);
#pragma unroll
            for (int i = 0; i < 8; i++) {
                int r = r0 + half * 8 + i;
                float2 p0 = unpack2(acc[i][0]);
                float2 p1 = unpack2(acc[i][1]);
                *(float2*)&h3s[r * S_H3 + cs] =
                    make_float2(fmaxf(p0.x + p0.y, 0.f), fmaxf(p1.x + p1.y, 0.f));
            }
        }
    }
    __syncthreads();

    for (int i = t; i < ROWS * GCOMP * DDIM; i += THREADS)
        gums[i] = gumbel[row0 * (GCOMP * DDIM) + i];

    // phase 4: K=200, 320 cols (300 real), 20 units; houts UNswizzled
    for (int u = w; u < 20; u += 8) {
        int r0 = (u & 1) * 16;
        int cb = (u >> 1) * 32 + slot * 2;
        unsigned long long bi0 = pack2(g_bh[cb], 0.f);
        unsigned long long bi1 = pack2(g_bh[cb + 1], 0.f);
#pragma unroll
        for (int i = 0; i < 8; i++) { acc[i][0] = bi0; acc[i][1] = bi1; }
        gemm32<H3, S_H3, NHEADP>(h3s + r0 * S_H3, half, g_Whp, cb, acc);
        if (cb < NHEAD) {
#pragma unroll
            for (int i = 0; i < 8; i++) {
                int r = r0 + half * 8 + i;
                float2 p0 = unpack2(acc[i][0]);
                float2 p1 = unpack2(acc[i][1]);
                *(float2*)&houts[r * S_HO + cb] =
                    make_float2(p0.x + p0.y, p1.x + p1.y);
            }
        }
    }
    __syncthreads();

    // phase 5: Gumbel-argmax, select, emit
    if (t < ROWS * DDIM) {
        int r = t >> 2, d = t & 3;
        const float* ho = houts + r * S_HO;
        const float* gu = gums + r * (GCOMP * DDIM);
        float best = -CUDART_INF_F;
        int bi = 0;
#pragma unroll
        for (int g = 0; g < GCOMP; g++) {
            float pai = fabsf(ho[200 + g * 4 + d]);
            float sc = logf(pai + 1e-12f) + gu[g * 4 + d];
            if (sc > best) { best = sc; bi = g; }
        }
        float mu = ho[bi * 4 + d];
        float sg = fabsf(ho[100 + bi * 4 + d]);
        int gi = (row0 + r) * 4 + d;
        out[gi] = fmaf(randv[gi], sg, mu);
    }
}

// inputs: 0:x0 1:rand 2:gumbel 3:W1 4:b1 5:W2 6:b2 7:W3 8:b3
//         9:Wmu 10:bmu 11:Wsig 12:bsig 13:Wpai 14:bpai
extern "C" void kernel_launch(void* const* d_in, const int* in_sizes, int n_in,
                              void* d_out, int out_size)
{
    const float* x0    = (const float*)d_in[0];
    const float* randv = (const float*)d_in[1];
    const float* gumb  = (const float*)d_in[2];
    const float* W1    = (const float*)d_in[3];
    const float* b1    = (const float*)d_in[4];
    const float* W2    = (const float*)d_in[5];
    const float* b2    = (const float*)d_in[6];
    const float* W3    = (const float*)d_in[7];
    const float* b3    = (const float*)d_in[8];
    const float* Wmu   = (const float*)d_in[9];
    const float* bmu   = (const float*)d_in[10];
    const float* Wsig  = (const float*)d_in[11];
    const float* bsig  = (const float*)d_in[12];
    const float* Wpai  = (const float*)d_in[13];
    const float* bpai  = (const float*)d_in[14];
    float* out = (float*)d_out;

    cudaFuncSetAttribute(mdn_kernel,
                         cudaFuncAttributeMaxDynamicSharedMemorySize, SMEM_BYTES);

    int prep_elems = (H1 / 2) * H2 * 2 + (H2 / 2) * H3P * 2
                   + (H3 / 2) * NHEADP * 2 + H3P + NHEADP;
    int prep_blocks = (prep_elems + 255) / 256;
    prep_kernel<<<prep_blocks, 256>>>(W2, W3, Wmu, Wsig, Wpai, b3,
                                      bmu, bsig, bpai);

    int grid = BATCH / ROWS;   // 8192
    mdn_kernel<<<grid, THREADS, SMEM_BYTES>>>(x0, randv, gumb, W1, b1, b2, out);
}

// round 10
// speedup vs baseline: 1.7548x; 1.1424x over previous
#include <cuda_runtime.h>
#include <math_constants.h>

#define BATCH   262144
#define GCOMP   25
#define DDIM    4
#define H1      128
#define H2      256
#define H3      200
#define NHEAD   300
#define H3P     224
#define NHEADP  320

#define ROWS    16
#define THREADS 256

// ---- packed f32x2 helpers ----
__device__ __forceinline__ void ffma2(unsigned long long& a,
                                      unsigned long long x,
                                      unsigned long long w) {
    asm("fma.rn.f32x2 %0, %1, %2, %0;" : "+l"(a) : "l"(x), "l"(w));
}
__device__ __forceinline__ unsigned long long pack2(float lo, float hi) {
    unsigned long long r;
    asm("mov.b64 %0, {%1, %2};" : "=l"(r) : "f"(lo), "f"(hi));
    return r;
}
__device__ __forceinline__ float2 unpack2(unsigned long long a) {
    float2 f;
    asm("mov.b64 {%0, %1}, %2;" : "=f"(f.x), "=f"(f.y) : "l"(a));
    return f;
}

// ---- k-pair-major packed weights: gWp[kp][c][j] = W[c][2kp+j] ----
__device__ __align__(16) float g_W2p[(H1 / 2) * H2 * 2];
__device__ __align__(16) float g_W3p[(H2 / 2) * H3P * 2];
__device__ __align__(16) float g_Whp[(H3 / 2) * NHEADP * 2];
__device__ __align__(16) float g_b3p[H3P];
__device__ __align__(16) float g_bh [NHEADP];

__global__ void prep_kernel(const float* __restrict__ W2,
                            const float* __restrict__ W3,
                            const float* __restrict__ Wmu,
                            const float* __restrict__ Wsig,
                            const float* __restrict__ Wpai,
                            const float* __restrict__ b3,
                            const float* __restrict__ bmu,
                            const float* __restrict__ bsig,
                            const float* __restrict__ bpai)
{
    const int t = blockIdx.x * blockDim.x + threadIdx.x;
    const int N2 = (H1 / 2) * H2 * 2;
    const int N3 = (H2 / 2) * H3P * 2;
    const int Nh = (H3 / 2) * NHEADP * 2;

    if (t < N2) {
        int kp = t / (H2 * 2), r = t % (H2 * 2);
        int c = r >> 1, j = r & 1;
        g_W2p[t] = W2[c * H1 + 2 * kp + j];
    }
    {
        int t2 = t - N2;
        if (t2 >= 0 && t2 < N3) {
            int kp = t2 / (H3P * 2), r = t2 % (H3P * 2);
            int c = r >> 1, j = r & 1;
            g_W3p[t2] = (c < H3) ? W3[c * H2 + 2 * kp + j] : 0.f;
        }
    }
    {
        int t3 = t - N2 - N3;
        if (t3 >= 0 && t3 < Nh) {
            int kp = t3 / (NHEADP * 2), r = t3 % (NHEADP * 2);
            int o = r >> 1, j = r & 1;
            float v = 0.f;
            if (o < NHEAD) {
                int h = o / 100, rem = o % 100;
                const float* W = (h == 0) ? Wmu : ((h == 1) ? Wsig : Wpai);
                v = W[rem * H3 + 2 * kp + j];
            }
            g_Whp[t3] = v;
        }
    }
    {
        int t4 = t - N2 - N3 - Nh;
        if (t4 >= 0 && t4 < H3P)
            g_b3p[t4] = (t4 < H3) ? b3[t4] : 0.f;
    }
    {
        int t5 = t - N2 - N3 - Nh - H3P;
        if (t5 >= 0 && t5 < NHEADP) {
            float v = 0.f;
            if (t5 < NHEAD) {
                int h = t5 / 100, rem = t5 % 100;
                const float* bb = (h == 0) ? bmu : ((h == 1) ? bsig : bpai);
                v = bb[rem];
            }
            g_bh[t5] = v;
        }
    }
}

// ---- SMEM layout (ROWS=16). Activations stored with quad XOR swizzle:
//      logical col c of row r lives at c ^ (4*((r>>3)&1)). ----
#define S_H1 128
#define S_H2 256
#define S_H3 224
#define S_HO 320

#define O_H2    0                       // 16*256 = 4096
#define O_H1    4096                    // 16*128 = 2048 -> 6144
#define O_H3    6144                    // 16*224 = 3584 -> 9728
#define O_HOUT  0                       // 16*320 = 5120 (inside 6144)
#define O_GUM   9728                    // 16*100 = 1600 -> 11328
#define O_X0    11328                   // 48 -> 11376
#define SMEM_FLOATS 11376
#define SMEM_BYTES  (SMEM_FLOATS * 4)   // 45504 B -> 3 blocks/SM (w/ 85 regs)

// One 16x32 unit: lane = 8 rows x 2 cols, k-pair FFMA2 accumulation.
template<int K, int SA, int CT>
__device__ __forceinline__ void gemm32(const float* __restrict__ act,
                                       int half,
                                       const float* __restrict__ wp,
                                       int cb,
                                       unsigned long long (&acc)[8][2])
{
    const float* pE = act + half * (8 * SA + 4);       // logical even quads
    const float* pO = act + half * (8 * SA - 4) + 4;   // logical odd quads
    const float* wb = wp + cb * 2;

#pragma unroll 2
    for (int c8 = 0; c8 < K / 8; c8++) {
        const float* w = wb + (4 * c8) * (CT * 2);
        ulonglong2 w0 = *(const ulonglong2*)(w);
        ulonglong2 w1 = *(const ulonglong2*)(w + CT * 2);
        ulonglong2 w2 = *(const ulonglong2*)(w + CT * 4);
        ulonglong2 w3 = *(const ulonglong2*)(w + CT * 6);
#pragma unroll
        for (int i = 0; i < 8; i++) {
            ulonglong2 xe = *(const ulonglong2*)(pE + i * SA + c8 * 8);
            ulonglong2 xo = *(const ulonglong2*)(pO + i * SA + c8 * 8);
            ffma2(acc[i][0], xe.x, w0.x); ffma2(acc[i][1], xe.x, w0.y);
            ffma2(acc[i][0], xe.y, w1.x); ffma2(acc[i][1], xe.y, w1.y);
            ffma2(acc[i][0], xo.x, w2.x); ffma2(acc[i][1], xo.x, w2.y);
            ffma2(acc[i][0], xo.y, w3.x); ffma2(acc[i][1], xo.y, w3.y);
        }
    }
}

__global__ __launch_bounds__(THREADS, 3)
void mdn_kernel(const float* __restrict__ x0,
                const float* __restrict__ randv,
                const float* __restrict__ gumbel,
                const float* __restrict__ W1,
                const float* __restrict__ b1,
                const float* __restrict__ b2,
                float* __restrict__ out)
{
    extern __shared__ float sm[];
    float* h1s   = sm + O_H1;
    float* h2s   = sm + O_H2;
    float* h3s   = sm + O_H3;
    float* houts = sm + O_HOUT;
    float* gums  = sm + O_GUM;
    float* x0s   = sm + O_X0;

    const int t    = threadIdx.x;
    const int w    = t >> 5;
    const int lane = t & 31;
    const int half = lane >> 4;
    const int slot = lane & 15;
    const int row0 = blockIdx.x * ROWS;

    if (t < ROWS * 3) x0s[t] = x0[row0 * 3 + t];
    __syncthreads();

    // phase 1: h1 = relu(x0 @ W1^T + b1), swizzled store (16x128 = 2048 outs)
#pragma unroll
    for (int i = 0; i < (ROWS * H1) / THREADS; i++) {
        int o = t + i * THREADS;
        int r = o >> 7;
        int c = o & 127;
        float acc1 = b1[c];
        acc1 = fmaf(x0s[r * 3 + 0], W1[c * 3 + 0], acc1);
        acc1 = fmaf(x0s[r * 3 + 1], W1[c * 3 + 1], acc1);
        acc1 = fmaf(x0s[r * 3 + 2], W1[c * 3 + 2], acc1);
        int cs = c ^ ((((unsigned)r >> 3) & 1) << 2);
        h1s[r * S_H1 + cs] = fmaxf(acc1, 0.f);
    }
    __syncthreads();

    unsigned long long acc[8][2];

    // phase 2: K=128, 256 cols, 8 units (1 per warp)
    {
        int cb = w * 32 + slot * 2;
        unsigned long long bi0 = pack2(b2[cb], 0.f);
        unsigned long long bi1 = pack2(b2[cb + 1], 0.f);
#pragma unroll
        for (int i = 0; i < 8; i++) { acc[i][0] = bi0; acc[i][1] = bi1; }
        gemm32<H1, S_H1, H2>(h1s, half, g_W2p, cb, acc);
        int cs = cb ^ (half << 2);
#pragma unroll
        for (int i = 0; i < 8; i++) {
            int r = half * 8 + i;
            float2 p0 = unpack2(acc[i][0]);
            float2 p1 = unpack2(acc[i][1]);
            *(float2*)&h2s[r * S_H2 + cs] =
                make_float2(fmaxf(p0.x + p0.y, 0.f), fmaxf(p1.x + p1.y, 0.f));
        }
    }
    __syncthreads();

    // phase 3: K=256, 224 cols (200 real), 7 units (warp 7 idle)
    if (w < 7) {
        int cb = w * 32 + slot * 2;
        unsigned long long bi0 = pack2(g_b3p[cb], 0.f);
        unsigned long long bi1 = pack2(g_b3p[cb + 1], 0.f);
#pragma unroll
        for (int i = 0; i < 8; i++) { acc[i][0] = bi0; acc[i][1] = bi1; }
        gemm32<H2, S_H2, H3P>(h2s, half, g_W3p, cb, acc);
        if (cb < H3) {
            int cs = cb ^ (half << 2);
#pragma unroll
            for (int i = 0; i < 8; i++) {
                int r = half * 8 + i;
                float2 p0 = unpack2(acc[i][0]);
                float2 p1 = unpack2(acc[i][1]);
                *(float2*)&h3s[r * S_H3 + cs] =
                    make_float2(fmaxf(p0.x + p0.y, 0.f), fmaxf(p1.x + p1.y, 0.f));
            }
        }
    }
    __syncthreads();

    for (int i = t; i < ROWS * GCOMP * DDIM; i += THREADS)
        gums[i] = gumbel[row0 * (GCOMP * DDIM) + i];

    // phase 4: K=200, 320 cols (300 real), 10 units (warps 0,1 do 2)
    for (int u = w; u < 10; u += 8) {
        int cb = u * 32 + slot * 2;
        unsigned long long bi0 = pack2(g_bh[cb], 0.f);
        unsigned long long bi1 = pack2(g_bh[cb + 1], 0.f);
#pragma unroll
        for (int i = 0; i < 8; i++) { acc[i][0] = bi0; acc[i][1] = bi1; }
        gemm32<H3, S_H3, NHEADP>(h3s, half, g_Whp, cb, acc);
        if (cb < NHEAD) {
#pragma unroll
            for (int i = 0; i < 8; i++) {
                int r = half * 8 + i;
                float2 p0 = unpack2(acc[i][0]);
                float2 p1 = unpack2(acc[i][1]);
                *(float2*)&houts[r * S_HO + cb] =
                    make_float2(p0.x + p0.y, p1.x + p1.y);
            }
        }
    }
    __syncthreads();

    // phase 5: Gumbel-argmax, select, emit (64 threads active)
    if (t < ROWS * DDIM) {
        int r = t >> 2, d = t & 3;
        const float* ho = houts + r * S_HO;
        const float* gu = gums + r * (GCOMP * DDIM);
        float best = -CUDART_INF_F;
        int bi = 0;
#pragma unroll
        for (int g = 0; g < GCOMP; g++) {
            float pai = fabsf(ho[200 + g * 4 + d]);
            float sc = logf(pai + 1e-12f) + gu[g * 4 + d];
            if (sc > best) { best = sc; bi = g; }
        }
        float mu = ho[bi * 4 + d];
        float sg = fabsf(ho[100 + bi * 4 + d]);
        int gi = (row0 + r) * 4 + d;
        out[gi] = fmaf(randv[gi], sg, mu);
    }
}

// inputs: 0:x0 1:rand 2:gumbel 3:W1 4:b1 5:W2 6:b2 7:W3 8:b3
//         9:Wmu 10:bmu 11:Wsig 12:bsig 13:Wpai 14:bpai
extern "C" void kernel_launch(void* const* d_in, const int* in_sizes, int n_in,
                              void* d_out, int out_size)
{
    const float* x0    = (const float*)d_in[0];
    const float* randv = (const float*)d_in[1];
    const float* gumb  = (const float*)d_in[2];
    const float* W1    = (const float*)d_in[3];
    const float* b1    = (const float*)d_in[4];
    const float* W2    = (const float*)d_in[5];
    const float* b2    = (const float*)d_in[6];
    const float* W3    = (const float*)d_in[7];
    const float* b3    = (const float*)d_in[8];
    const float* Wmu   = (const float*)d_in[9];
    const float* bmu   = (const float*)d_in[10];
    const float* Wsig  = (const float*)d_in[11];
    const float* bsig  = (const float*)d_in[12];
    const float* Wpai  = (const float*)d_in[13];
    const float* bpai  = (const float*)d_in[14];
    float* out = (float*)d_out;

    cudaFuncSetAttribute(mdn_kernel,
                         cudaFuncAttributeMaxDynamicSharedMemorySize, SMEM_BYTES);

    int prep_elems = (H1 / 2) * H2 * 2 + (H2 / 2) * H3P * 2
                   + (H3 / 2) * NHEADP * 2 + H3P + NHEADP;
    int prep_blocks = (prep_elems + 255) / 256;
    prep_kernel<<<prep_blocks, 256>>>(W2, W3, Wmu, Wsig, Wpai, b3,
                                      bmu, bsig, bpai);

    int grid = BATCH / ROWS;   // 16384
    mdn_kernel<<<grid, THREADS, SMEM_BYTES>>>(x0, randv, gumb, W1, b1, b2, out);
}